// round 7
// baseline (speedup 1.0000x reference)
#include <cuda_runtime.h>
#include <math.h>
#include <stdint.h>

// Problem constants (fixed by the dataset)
#define NS   20000      // source nodes
#define NT   20000      // target nodes
#define EE   100000     // edges per type
#define FF   128        // input features
#define HCC  256        // H*C
#define TT   6          // edge types
#define NEG_SLOPE 0.2f

// ---------------- scratch (static device globals; no allocation) -------------
__device__ __align__(16) float g_hs1 [(size_t)NS*HCC];
__device__ __align__(16) float g_hd1 [(size_t)NT*HCC];
__device__ __align__(16) float g_h1  [(size_t)NT*HCC];   // layer-1 aggregated (pre-relu)
__device__ __align__(16) float g_hs2 [(size_t)NS*HCC];
__device__ __align__(16) float g_hd2 [(size_t)NT*HCC];
__device__ __align__(16) float g_out2[(size_t)NT*HCC];   // layer-2 aggregated
__device__ __align__(16) float g_escore[(size_t)EE*4];
__device__ __align__(16) float g_wbuf  [(size_t)EE*4];
__device__ unsigned g_emax1[NT*4];
__device__ unsigned g_emax2[NT*4];
__device__ float    g_denom1[NT*4];
__device__ float    g_denom2[NT*4];
__device__ float    g_pooled[HCC];
__device__ float    g_agg[8];

// monotone float <-> uint encoding for atomicMax on floats
__device__ __forceinline__ unsigned fenc(float f) {
    unsigned u = __float_as_uint(f);
    return u ^ ((unsigned)((int)u >> 31) | 0x80000000u);
}
__device__ __forceinline__ float fdec(unsigned u) {
    unsigned b = (u & 0x80000000u) ? (u ^ 0x80000000u) : ~u;
    return __uint_as_float(b);
}
#define ENC_NEG_INF 0x007FFFFFu   // fenc(-inf)

// ---------------- init: zero accumulators, set segment-max identity ----------
__global__ void init_kernel() {
    size_t stride = (size_t)gridDim.x * blockDim.x;
    size_t i0 = (size_t)blockIdx.x * blockDim.x + threadIdx.x;
    for (size_t i = i0; i < (size_t)NT * HCC; i += stride) { g_h1[i] = 0.f; g_out2[i] = 0.f; }
    for (size_t i = i0; i < (size_t)NT * 4; i += stride) {
        g_denom1[i] = 0.f; g_denom2[i] = 0.f;
        g_emax1[i] = ENC_NEG_INF; g_emax2[i] = ENC_NEG_INF;
    }
    if (i0 < HCC) g_pooled[i0] = 0.f;
    if (i0 < 8)   g_agg[i0] = 0.f;
}

// ---------------- SGEMM: C[M,256] = op(A[M,K]) @ B[K,256] --------------------
// MASK_A: multiply row r of A by mask[r].  RELU_A: relu on A elements.
// Block = 256 threads, tile 128(M) x 128(N) x 16(K), 8x8 microtile (4+4 split).
// Mainloop: 4x LDS.128 per 64 FFMA per k-step -> FMA-pipe bound (was L1-bound).
template<int MASK_A, int RELU_A>
__global__ void sgemm128(const float* __restrict__ A, const float* __restrict__ B,
                         float* __restrict__ C, const float* __restrict__ mask,
                         int M, int K)
{
    __shared__ __align__(16) float As[16][132];   // transposed A tile [k][m]
    __shared__ __align__(16) float Bs[16][132];   // B tile [k][n]
    const int tid = threadIdx.x;                  // 256 threads
    const int bm = blockIdx.y * 128;
    const int bn = blockIdx.x * 128;
    const int ty = tid >> 4;                      // 0..15
    const int tx = tid & 15;                      // 0..15
    const int rm0 = ty * 4;                       // rows rm0..rm0+3
    const int rm1 = rm0 + 64;                     // rows rm1..rm1+3
    const int cn0 = tx * 4;                       // cols cn0..cn0+3
    const int cn1 = cn0 + 64;                     // cols cn1..cn1+3

    float acc[8][8];
#pragma unroll
    for (int i = 0; i < 8; i++)
#pragma unroll
        for (int j = 0; j < 8; j++) acc[i][j] = 0.f;

    // A-load mapping: thread loads rows ar0 = tid>>2 and ar1 = ar0+64, 4 k's each
    const int ar0 = tid >> 2;
    const int ar1 = ar0 + 64;
    const int ac4 = (tid & 3) << 2;               // k-offset within tile: 0,4,8,12
    const int gr0 = bm + ar0, gr1 = bm + ar1;
    const bool av0 = gr0 < M, av1 = gr1 < M;
    float mv0 = 1.f, mv1 = 1.f;
    if (MASK_A) {
        mv0 = av0 ? __ldg(mask + gr0) : 0.f;
        mv1 = av1 ? __ldg(mask + gr1) : 0.f;
    }
    const float* Arow0 = A + (size_t)gr0 * K;
    const float* Arow1 = A + (size_t)gr1 * K;

    // B-load mapping: thread loads rows br0 = tid>>5 and br0+8, 4 n's each
    const int br0 = tid >> 5;                     // 0..7
    const int bc4 = (tid & 31) << 2;              // 0..124

    for (int k0 = 0; k0 < K; k0 += 16) {
        // ---- A tile (transposed store) ----
        float4 a0 = av0 ? *(const float4*)(Arow0 + k0 + ac4) : make_float4(0.f,0.f,0.f,0.f);
        float4 a1 = av1 ? *(const float4*)(Arow1 + k0 + ac4) : make_float4(0.f,0.f,0.f,0.f);
        if (MASK_A) {
            a0.x *= mv0; a0.y *= mv0; a0.z *= mv0; a0.w *= mv0;
            a1.x *= mv1; a1.y *= mv1; a1.z *= mv1; a1.w *= mv1;
        }
        if (RELU_A) {
            a0.x = fmaxf(a0.x,0.f); a0.y = fmaxf(a0.y,0.f); a0.z = fmaxf(a0.z,0.f); a0.w = fmaxf(a0.w,0.f);
            a1.x = fmaxf(a1.x,0.f); a1.y = fmaxf(a1.y,0.f); a1.z = fmaxf(a1.z,0.f); a1.w = fmaxf(a1.w,0.f);
        }
        As[ac4 + 0][ar0] = a0.x; As[ac4 + 1][ar0] = a0.y;
        As[ac4 + 2][ar0] = a0.z; As[ac4 + 3][ar0] = a0.w;
        As[ac4 + 0][ar1] = a1.x; As[ac4 + 1][ar1] = a1.y;
        As[ac4 + 2][ar1] = a1.z; As[ac4 + 3][ar1] = a1.w;

        // ---- B tile ----
        float4 b0 = *(const float4*)(B + (size_t)(k0 + br0) * HCC + bn + bc4);
        float4 b1 = *(const float4*)(B + (size_t)(k0 + br0 + 8) * HCC + bn + bc4);
        *(float4*)&Bs[br0][bc4]     = b0;
        *(float4*)&Bs[br0 + 8][bc4] = b1;
        __syncthreads();

#pragma unroll
        for (int k = 0; k < 16; k++) {
            const float4 va0 = *(const float4*)&As[k][rm0];   // LDS.128
            const float4 va1 = *(const float4*)&As[k][rm1];   // LDS.128
            const float4 vb0 = *(const float4*)&Bs[k][cn0];   // LDS.128
            const float4 vb1 = *(const float4*)&Bs[k][cn1];   // LDS.128
            const float ar[8] = {va0.x, va0.y, va0.z, va0.w, va1.x, va1.y, va1.z, va1.w};
            const float br[8] = {vb0.x, vb0.y, vb0.z, vb0.w, vb1.x, vb1.y, vb1.z, vb1.w};
#pragma unroll
            for (int i = 0; i < 8; i++)
#pragma unroll
                for (int j = 0; j < 8; j++)
                    acc[i][j] = fmaf(ar[i], br[j], acc[i][j]);
        }
        __syncthreads();
    }

    // ---- epilogue: 16 float4 stores with row guards ----
#pragma unroll
    for (int half = 0; half < 2; half++) {
        const int rbase = bm + (half ? rm1 : rm0);
#pragma unroll
        for (int i = 0; i < 4; i++) {
            const int r = rbase + i;
            if (r < M) {
                const int ai = half * 4 + i;
                float4 v0 = make_float4(acc[ai][0], acc[ai][1], acc[ai][2], acc[ai][3]);
                float4 v1 = make_float4(acc[ai][4], acc[ai][5], acc[ai][6], acc[ai][7]);
                *(float4*)(C + (size_t)r * HCC + bn + cn0) = v0;
                *(float4*)(C + (size_t)r * HCC + bn + cn1) = v1;
            }
        }
    }
}

// ---------------- edge pass 1: GATv2 scores + segment max --------------------
// one warp per edge; lane l handles 8 channels, head = l/8 (4 heads x 8 lanes).
__global__ void edge_score_max(const int* __restrict__ src, const int* __restrict__ dst,
                               const float* __restrict__ hs, const float* __restrict__ hd,
                               const float* __restrict__ avec,
                               float* __restrict__ escore, unsigned* __restrict__ emax)
{
    int gw = (int)((blockIdx.x * (size_t)blockDim.x + threadIdx.x) >> 5);
    if (gw >= EE) return;
    int lane = threadIdx.x & 31;
    int s = __ldg(src + gw), d = __ldg(dst + gw);
    const float4* ps = (const float4*)(hs + (size_t)s * HCC);
    const float4* pd = (const float4*)(hd + (size_t)d * HCC);
    const float4* pa = (const float4*)avec;
    float sum = 0.f;
#pragma unroll
    for (int q = 0; q < 2; q++) {
        int idx = lane * 2 + q;
        float4 va = __ldg(pa + idx);
        float4 vs = ps[idx];
        float4 vd = pd[idx];
        float z;
        z = vs.x + vd.x; z = z > 0.f ? z : NEG_SLOPE * z; sum = fmaf(z, va.x, sum);
        z = vs.y + vd.y; z = z > 0.f ? z : NEG_SLOPE * z; sum = fmaf(z, va.y, sum);
        z = vs.z + vd.z; z = z > 0.f ? z : NEG_SLOPE * z; sum = fmaf(z, va.z, sum);
        z = vs.w + vd.w; z = z > 0.f ? z : NEG_SLOPE * z; sum = fmaf(z, va.w, sum);
    }
    // reduce 8 lanes within each head (lanes [8h, 8h+8))
    sum += __shfl_down_sync(0xffffffffu, sum, 4, 8);
    sum += __shfl_down_sync(0xffffffffu, sum, 2, 8);
    sum += __shfl_down_sync(0xffffffffu, sum, 1, 8);
    if ((lane & 7) == 0) {
        int h = lane >> 3;
        escore[(size_t)gw * 4 + h] = sum;
        atomicMax(&emax[(size_t)d * 4 + h], fenc(sum));
    }
}

// ---------------- edge pass 2: exp(e - max) * mask, segment denom ------------
__global__ void edge_softmax_denom(const int* __restrict__ dst,
                                   const float* __restrict__ escore,
                                   const unsigned* __restrict__ emax,
                                   const float* __restrict__ emask,
                                   float* __restrict__ w, float* __restrict__ denom)
{
    int e = blockIdx.x * blockDim.x + threadIdx.x;
    if (e >= EE) return;
    int d = __ldg(dst + e);
    float m = __ldg(emask + e);
#pragma unroll
    for (int h = 0; h < 4; h++) {
        float mx = fdec(emax[(size_t)d * 4 + h]);
        float ww = expf(escore[(size_t)e * 4 + h] - mx) * m;
        w[(size_t)e * 4 + h] = ww;
        atomicAdd(&denom[(size_t)d * 4 + h], ww);
    }
}

// ---------------- edge pass 3: out[dst] += alpha * hs[src] -------------------
__global__ void edge_aggregate(const int* __restrict__ src, const int* __restrict__ dst,
                               const float* __restrict__ hs, const float* __restrict__ w,
                               const float* __restrict__ denom, float* __restrict__ out)
{
    int gw = (int)((blockIdx.x * (size_t)blockDim.x + threadIdx.x) >> 5);
    if (gw >= EE) return;
    int lane = threadIdx.x & 31;
    int s = __ldg(src + gw), d = __ldg(dst + gw);
    float alpha = 0.f;
    if ((lane & 7) == 0) {
        int h = lane >> 3;
        alpha = w[(size_t)gw * 4 + h] / (denom[(size_t)d * 4 + h] + 1e-16f);
    }
    alpha = __shfl_sync(0xffffffffu, alpha, lane & 24);   // broadcast head leader
    const float4* ps = (const float4*)(hs + (size_t)s * HCC);
    float* po = out + (size_t)d * HCC;
#pragma unroll
    for (int q = 0; q < 2; q++) {
        int idx = lane * 2 + q;
        float4 v = ps[idx];
        asm volatile("red.global.add.v4.f32 [%0], {%1,%2,%3,%4};"
                     :: "l"(po + idx * 4),
                        "f"(alpha * v.x), "f"(alpha * v.y),
                        "f"(alpha * v.z), "f"(alpha * v.w)
                     : "memory");
    }
}

// ---------------- mean-pool over nodes (column sums) -------------------------
__global__ void pool_kernel(const float* __restrict__ x, float* __restrict__ pooled)
{
    float s = 0.f;
    for (int r = blockIdx.x; r < NT; r += gridDim.x)
        s += x[(size_t)r * HCC + threadIdx.x];
    atomicAdd(&pooled[threadIdx.x], s);
}

// ---------------- edge_attr per-type means -----------------------------------
__global__ void edge_attr_agg(const float* __restrict__ ea, float* __restrict__ agg)
{
    int t = blockIdx.y;
    const float* p = ea + (size_t)t * EE;
    float s = 0.f;
    for (int i = blockIdx.x * blockDim.x + threadIdx.x; i < EE; i += gridDim.x * blockDim.x)
        s += p[i];
    __shared__ float sm[256];
    sm[threadIdx.x] = s;
    __syncthreads();
    for (int o = 128; o > 0; o >>= 1) {
        if (threadIdx.x < o) sm[threadIdx.x] += sm[threadIdx.x + o];
        __syncthreads();
    }
    if (threadIdx.x == 0) atomicAdd(&agg[t], sm[0]);
}

// ---------------- classifier head --------------------------------------------
__global__ void finalize_kernel(const float* __restrict__ Wc, const float* __restrict__ bc,
                                float* __restrict__ out)
{
    __shared__ float sm[256];
    int t = threadIdx.x;
    sm[t] = g_pooled[t] * (1.0f / NT) * Wc[t];
    __syncthreads();
    for (int o = 128; o > 0; o >>= 1) {
        if (t < o) sm[t] += sm[t + o];
        __syncthreads();
    }
    if (t == 0) {
        float s = sm[0];
#pragma unroll
        for (int k = 0; k < TT; k++) s += g_agg[k] * (1.0f / EE) * Wc[HCC + k];
        s += bc[0];
        out[0] = 1.f / (1.f + expf(-s));
    }
}

// ---------------- host orchestration -----------------------------------------
extern "C" void kernel_launch(void* const* d_in, const int* in_sizes, int n_in,
                              void* d_out, int out_size)
{
    (void)in_sizes; (void)n_in; (void)out_size;
    const float* xs    = (const float*)d_in[0];
    const float* xt5   = (const float*)d_in[1] + (size_t)(TT - 1) * NT * FF;
    const float* ea    = (const float*)d_in[2];
    const float* nmask = (const float*)d_in[3];
    const float* emask = (const float*)d_in[4];
    const int*   ei    = (const int*)d_in[5];
    const int*   src5  = ei + (size_t)(TT - 1) * 2 * EE;
    const int*   dst5  = src5 + EE;
    const float* W1s5  = (const float*)d_in[6]  + (size_t)(TT - 1) * FF * HCC;
    const float* W1d5  = (const float*)d_in[7]  + (size_t)(TT - 1) * FF * HCC;
    const float* a1_5  = (const float*)d_in[8]  + (size_t)(TT - 1) * HCC;
    const float* W2s5  = (const float*)d_in[9]  + (size_t)(TT - 1) * FF * HCC;
    const float* W2d5  = (const float*)d_in[10] + (size_t)(TT - 1) * HCC * HCC;
    const float* a2_5  = (const float*)d_in[11] + (size_t)(TT - 1) * HCC;
    const float* Wc    = (const float*)d_in[12];
    const float* bc    = (const float*)d_in[13];
    float* out = (float*)d_out;

    float *hs1, *hd1, *h1, *hs2, *hd2, *out2, *esc, *wb, *den1, *den2, *pooled, *agg;
    unsigned *emx1, *emx2;
    cudaGetSymbolAddress((void**)&hs1,    g_hs1);
    cudaGetSymbolAddress((void**)&hd1,    g_hd1);
    cudaGetSymbolAddress((void**)&h1,     g_h1);
    cudaGetSymbolAddress((void**)&hs2,    g_hs2);
    cudaGetSymbolAddress((void**)&hd2,    g_hd2);
    cudaGetSymbolAddress((void**)&out2,   g_out2);
    cudaGetSymbolAddress((void**)&esc,    g_escore);
    cudaGetSymbolAddress((void**)&wb,     g_wbuf);
    cudaGetSymbolAddress((void**)&den1,   g_denom1);
    cudaGetSymbolAddress((void**)&den2,   g_denom2);
    cudaGetSymbolAddress((void**)&emx1,   g_emax1);
    cudaGetSymbolAddress((void**)&emx2,   g_emax2);
    cudaGetSymbolAddress((void**)&pooled, g_pooled);
    cudaGetSymbolAddress((void**)&agg,    g_agg);

    dim3 gemm_grid(HCC / 128, (NT + 127) / 128);                 // (2, 157)
    const int EW_BLOCKS = (int)(((size_t)EE * 32 + 255) / 256);  // warp-per-edge kernels
    const int E_BLOCKS  = (EE + 255) / 256;

    init_kernel<<<1024, 256>>>();

    // layer-1 projections + layer-2 source projection (independent of layer 1)
    sgemm128<1, 0><<<gemm_grid, 256>>>(xs,  W1s5, hs1, nmask, NS, FF);
    sgemm128<1, 0><<<gemm_grid, 256>>>(xt5, W1d5, hd1, nmask, NT, FF);
    sgemm128<1, 0><<<gemm_grid, 256>>>(xs,  W2s5, hs2, nmask, NS, FF);

    // layer-1 attention
    edge_score_max<<<EW_BLOCKS, 256>>>(src5, dst5, hs1, hd1, a1_5, esc, emx1);
    edge_softmax_denom<<<E_BLOCKS, 256>>>(dst5, esc, emx1, emask, wb, den1);
    edge_aggregate<<<EW_BLOCKS, 256>>>(src5, dst5, hs1, wb, den1, h1);

    // layer-2 target projection: relu(h1) @ W2_dst  (relu folded into A-load)
    sgemm128<0, 1><<<gemm_grid, 256>>>(h1, W2d5, hd2, nullptr, NT, HCC);

    // layer-2 attention
    edge_score_max<<<EW_BLOCKS, 256>>>(src5, dst5, hs2, hd2, a2_5, esc, emx2);
    edge_softmax_denom<<<E_BLOCKS, 256>>>(dst5, esc, emx2, emask, wb, den2);
    edge_aggregate<<<EW_BLOCKS, 256>>>(src5, dst5, hs2, wb, den2, out2);

    // head
    pool_kernel<<<128, 256>>>(out2, pooled);
    edge_attr_agg<<<dim3(32, TT), 256>>>(ea, agg);
    finalize_kernel<<<1, 256>>>(Wc, bc, out);
}

// round 16
// speedup vs baseline: 1.0879x; 1.0879x over previous
#include <cuda_runtime.h>
#include <mma.h>
#include <math.h>
#include <stdint.h>

using namespace nvcuda;

// Problem constants (fixed by the dataset)
#define NS   20000      // source nodes
#define NT   20000      // target nodes
#define NPAD 20096      // padded to multiple of 128 for unguarded wmma stores
#define EE   100000     // edges per type
#define FF   128        // input features
#define HCC  256        // H*C
#define TT   6          // edge types
#define NEG_SLOPE 0.2f

// ---------------- scratch (static device globals; no allocation) -------------
// Node-feature buffers padded to NPAD rows: wmma epilogue writes whole 128-row
// tiles; pad rows are never read (edge indices < 20000, pool reads < NT).
__device__ __align__(16) float g_hs1 [(size_t)NPAD*HCC];
__device__ __align__(16) float g_hd1 [(size_t)NPAD*HCC];
__device__ __align__(16) float g_h1  [(size_t)NPAD*HCC];   // layer-1 aggregated (pre-relu)
__device__ __align__(16) float g_hs2 [(size_t)NPAD*HCC];
__device__ __align__(16) float g_hd2 [(size_t)NPAD*HCC];
__device__ __align__(16) float g_out2[(size_t)NPAD*HCC];   // layer-2 aggregated
__device__ __align__(16) float g_escore[(size_t)EE*4];
__device__ __align__(16) float g_wbuf  [(size_t)EE*4];
__device__ unsigned g_emax1[NT*4];
__device__ unsigned g_emax2[NT*4];
__device__ float    g_denom1[NT*4];
__device__ float    g_denom2[NT*4];
__device__ float    g_pooled[HCC];
__device__ float    g_agg[8];

// monotone float <-> uint encoding for atomicMax on floats
__device__ __forceinline__ unsigned fenc(float f) {
    unsigned u = __float_as_uint(f);
    return u ^ ((unsigned)((int)u >> 31) | 0x80000000u);
}
__device__ __forceinline__ float fdec(unsigned u) {
    unsigned b = (u & 0x80000000u) ? (u ^ 0x80000000u) : ~u;
    return __uint_as_float(b);
}
#define ENC_NEG_INF 0x007FFFFFu   // fenc(-inf)

// ---------------- init: zero accumulators, set segment-max identity ----------
__global__ void init_kernel() {
    size_t stride = (size_t)gridDim.x * blockDim.x;
    size_t i0 = (size_t)blockIdx.x * blockDim.x + threadIdx.x;
    for (size_t i = i0; i < (size_t)NT * HCC; i += stride) { g_h1[i] = 0.f; g_out2[i] = 0.f; }
    for (size_t i = i0; i < (size_t)NT * 4; i += stride) {
        g_denom1[i] = 0.f; g_denom2[i] = 0.f;
        g_emax1[i] = ENC_NEG_INF; g_emax2[i] = ENC_NEG_INF;
    }
    if (i0 < HCC) g_pooled[i0] = 0.f;
    if (i0 < 8)   g_agg[i0] = 0.f;
}

// ---------------- tf32 tensor-core GEMM: C[M,256] = op(A[M,K]) @ B[K,256] ----
// MASK_A: multiply row r of A by mask[r].  RELU_A: relu on A elements.
// Block = 256 threads (8 warps), tile 128(M) x 128(N) x 16(K).
// Warp tile 32x64 = 2x4 wmma m16n16k8 fragments, tf32 in / fp32 accumulate.
// Pads keep all rows 16B-aligned: lda=20 (80B rows), ldb=136 (544B rows).
template<int MASK_A, int RELU_A>
__global__ void sgemm_tc(const float* __restrict__ A, const float* __restrict__ B,
                         float* __restrict__ C, const float* __restrict__ mask,
                         int M, int K)
{
    __shared__ __align__(16) float As[128][20];   // [m][k], lda = 20
    __shared__ __align__(16) float Bs[16][136];   // [k][n], ldb = 136
    const int tid  = threadIdx.x;
    const int bm   = blockIdx.y * 128;
    const int bn   = blockIdx.x * 128;
    const int warp = tid >> 5;
    const int wm   = (warp >> 1) * 32;            // 0,32,64,96
    const int wn   = (warp & 1) * 64;             // 0,64

    wmma::fragment<wmma::accumulator, 16, 16, 8, float> acc[2][4];
#pragma unroll
    for (int i = 0; i < 2; i++)
#pragma unroll
        for (int j = 0; j < 4; j++) wmma::fill_fragment(acc[i][j], 0.f);

    // A-load mapping: rows ar0 = tid>>2 and ar0+64, k-offset (tid&3)*4
    const int ar0 = tid >> 2;
    const int ar1 = ar0 + 64;
    const int ac4 = (tid & 3) << 2;
    const int gr0 = bm + ar0, gr1 = bm + ar1;
    const bool av0 = gr0 < M, av1 = gr1 < M;
    float mv0 = 1.f, mv1 = 1.f;
    if (MASK_A) {
        mv0 = av0 ? __ldg(mask + gr0) : 0.f;
        mv1 = av1 ? __ldg(mask + gr1) : 0.f;
    }
    const float* Arow0 = A + (size_t)gr0 * K;
    const float* Arow1 = A + (size_t)gr1 * K;

    // B-load mapping: rows br0 = tid>>5 and br0+8, 4 n's at (tid&31)*4
    const int br0 = tid >> 5;
    const int bc4 = (tid & 31) << 2;

    for (int k0 = 0; k0 < K; k0 += 16) {
        float4 a0 = av0 ? *(const float4*)(Arow0 + k0 + ac4) : make_float4(0.f,0.f,0.f,0.f);
        float4 a1 = av1 ? *(const float4*)(Arow1 + k0 + ac4) : make_float4(0.f,0.f,0.f,0.f);
        if (MASK_A) {
            a0.x *= mv0; a0.y *= mv0; a0.z *= mv0; a0.w *= mv0;
            a1.x *= mv1; a1.y *= mv1; a1.z *= mv1; a1.w *= mv1;
        }
        if (RELU_A) {
            a0.x = fmaxf(a0.x,0.f); a0.y = fmaxf(a0.y,0.f); a0.z = fmaxf(a0.z,0.f); a0.w = fmaxf(a0.w,0.f);
            a1.x = fmaxf(a1.x,0.f); a1.y = fmaxf(a1.y,0.f); a1.z = fmaxf(a1.z,0.f); a1.w = fmaxf(a1.w,0.f);
        }
        *(float4*)&As[ar0][ac4] = a0;   // 80B row stride keeps 16B alignment
        *(float4*)&As[ar1][ac4] = a1;

        *(float4*)&Bs[br0    ][bc4] = *(const float4*)(B + (size_t)(k0 + br0    ) * HCC + bn + bc4);
        *(float4*)&Bs[br0 + 8][bc4] = *(const float4*)(B + (size_t)(k0 + br0 + 8) * HCC + bn + bc4);
        __syncthreads();

#pragma unroll
        for (int ks = 0; ks < 16; ks += 8) {
            wmma::fragment<wmma::matrix_a, 16, 16, 8, wmma::precision::tf32, wmma::row_major> af[2];
            wmma::fragment<wmma::matrix_b, 16, 16, 8, wmma::precision::tf32, wmma::row_major> bf[4];
#pragma unroll
            for (int i = 0; i < 2; i++) {
                wmma::load_matrix_sync(af[i], &As[wm + i * 16][ks], 20);
#pragma unroll
                for (int t = 0; t < af[i].num_elements; t++)
                    af[i].x[t] = wmma::__float_to_tf32(af[i].x[t]);
            }
#pragma unroll
            for (int j = 0; j < 4; j++) {
                wmma::load_matrix_sync(bf[j], &Bs[ks][wn + j * 16], 136);
#pragma unroll
                for (int t = 0; t < bf[j].num_elements; t++)
                    bf[j].x[t] = wmma::__float_to_tf32(bf[j].x[t]);
            }
#pragma unroll
            for (int i = 0; i < 2; i++)
#pragma unroll
                for (int j = 0; j < 4; j++)
                    wmma::mma_sync(acc[i][j], af[i], bf[j], acc[i][j]);
        }
        __syncthreads();
    }

    // epilogue: unguarded stores into NPAD-padded C
#pragma unroll
    for (int i = 0; i < 2; i++)
#pragma unroll
        for (int j = 0; j < 4; j++)
            wmma::store_matrix_sync(C + (size_t)(bm + wm + i * 16) * HCC + bn + wn + j * 16,
                                    acc[i][j], HCC, wmma::mem_row_major);
}

// ---------------- edge pass 1: GATv2 scores + segment max --------------------
// one warp per edge; lane l handles 8 channels, head = l/8 (4 heads x 8 lanes).
__global__ void edge_score_max(const int* __restrict__ src, const int* __restrict__ dst,
                               const float* __restrict__ hs, const float* __restrict__ hd,
                               const float* __restrict__ avec,
                               float* __restrict__ escore, unsigned* __restrict__ emax)
{
    int gw = (int)((blockIdx.x * (size_t)blockDim.x + threadIdx.x) >> 5);
    if (gw >= EE) return;
    int lane = threadIdx.x & 31;
    int s = __ldg(src + gw), d = __ldg(dst + gw);
    const float4* ps = (const float4*)(hs + (size_t)s * HCC);
    const float4* pd = (const float4*)(hd + (size_t)d * HCC);
    const float4* pa = (const float4*)avec;
    float sum = 0.f;
#pragma unroll
    for (int q = 0; q < 2; q++) {
        int idx = lane * 2 + q;
        float4 va = __ldg(pa + idx);
        float4 vs = ps[idx];
        float4 vd = pd[idx];
        float z;
        z = vs.x + vd.x; z = z > 0.f ? z : NEG_SLOPE * z; sum = fmaf(z, va.x, sum);
        z = vs.y + vd.y; z = z > 0.f ? z : NEG_SLOPE * z; sum = fmaf(z, va.y, sum);
        z = vs.z + vd.z; z = z > 0.f ? z : NEG_SLOPE * z; sum = fmaf(z, va.z, sum);
        z = vs.w + vd.w; z = z > 0.f ? z : NEG_SLOPE * z; sum = fmaf(z, va.w, sum);
    }
    // reduce 8 lanes within each head (lanes [8h, 8h+8))
    sum += __shfl_down_sync(0xffffffffu, sum, 4, 8);
    sum += __shfl_down_sync(0xffffffffu, sum, 2, 8);
    sum += __shfl_down_sync(0xffffffffu, sum, 1, 8);
    if ((lane & 7) == 0) {
        int h = lane >> 3;
        escore[(size_t)gw * 4 + h] = sum;
        atomicMax(&emax[(size_t)d * 4 + h], fenc(sum));
    }
}

// ---------------- edge pass 2: exp(e - max) * mask, segment denom ------------
__global__ void edge_softmax_denom(const int* __restrict__ dst,
                                   const float* __restrict__ escore,
                                   const unsigned* __restrict__ emax,
                                   const float* __restrict__ emask,
                                   float* __restrict__ w, float* __restrict__ denom)
{
    int e = blockIdx.x * blockDim.x + threadIdx.x;
    if (e >= EE) return;
    int d = __ldg(dst + e);
    float m = __ldg(emask + e);
#pragma unroll
    for (int h = 0; h < 4; h++) {
        float mx = fdec(emax[(size_t)d * 4 + h]);
        float ww = expf(escore[(size_t)e * 4 + h] - mx) * m;
        w[(size_t)e * 4 + h] = ww;
        atomicAdd(&denom[(size_t)d * 4 + h], ww);
    }
}

// ---------------- edge pass 3: out[dst] += alpha * hs[src] -------------------
__global__ void edge_aggregate(const int* __restrict__ src, const int* __restrict__ dst,
                               const float* __restrict__ hs, const float* __restrict__ w,
                               const float* __restrict__ denom, float* __restrict__ out)
{
    int gw = (int)((blockIdx.x * (size_t)blockDim.x + threadIdx.x) >> 5);
    if (gw >= EE) return;
    int lane = threadIdx.x & 31;
    int s = __ldg(src + gw), d = __ldg(dst + gw);
    float alpha = 0.f;
    if ((lane & 7) == 0) {
        int h = lane >> 3;
        alpha = w[(size_t)gw * 4 + h] / (denom[(size_t)d * 4 + h] + 1e-16f);
    }
    alpha = __shfl_sync(0xffffffffu, alpha, lane & 24);   // broadcast head leader
    const float4* ps = (const float4*)(hs + (size_t)s * HCC);
    float* po = out + (size_t)d * HCC;
#pragma unroll
    for (int q = 0; q < 2; q++) {
        int idx = lane * 2 + q;
        float4 v = ps[idx];
        asm volatile("red.global.add.v4.f32 [%0], {%1,%2,%3,%4};"
                     :: "l"(po + idx * 4),
                        "f"(alpha * v.x), "f"(alpha * v.y),
                        "f"(alpha * v.z), "f"(alpha * v.w)
                     : "memory");
    }
}

// ---------------- mean-pool over nodes (column sums) -------------------------
__global__ void pool_kernel(const float* __restrict__ x, float* __restrict__ pooled)
{
    float s = 0.f;
    for (int r = blockIdx.x; r < NT; r += gridDim.x)
        s += x[(size_t)r * HCC + threadIdx.x];
    atomicAdd(&pooled[threadIdx.x], s);
}

// ---------------- edge_attr per-type means -----------------------------------
__global__ void edge_attr_agg(const float* __restrict__ ea, float* __restrict__ agg)
{
    int t = blockIdx.y;
    const float* p = ea + (size_t)t * EE;
    float s = 0.f;
    for (int i = blockIdx.x * blockDim.x + threadIdx.x; i < EE; i += gridDim.x * blockDim.x)
        s += p[i];
    __shared__ float sm[256];
    sm[threadIdx.x] = s;
    __syncthreads();
    for (int o = 128; o > 0; o >>= 1) {
        if (threadIdx.x < o) sm[threadIdx.x] += sm[threadIdx.x + o];
        __syncthreads();
    }
    if (threadIdx.x == 0) atomicAdd(&agg[t], sm[0]);
}

// ---------------- classifier head --------------------------------------------
__global__ void finalize_kernel(const float* __restrict__ Wc, const float* __restrict__ bc,
                                float* __restrict__ out)
{
    __shared__ float sm[256];
    int t = threadIdx.x;
    sm[t] = g_pooled[t] * (1.0f / NT) * Wc[t];
    __syncthreads();
    for (int o = 128; o > 0; o >>= 1) {
        if (t < o) sm[t] += sm[t + o];
        __syncthreads();
    }
    if (t == 0) {
        float s = sm[0];
#pragma unroll
        for (int k = 0; k < TT; k++) s += g_agg[k] * (1.0f / EE) * Wc[HCC + k];
        s += bc[0];
        out[0] = 1.f / (1.f + expf(-s));
    }
}

// ---------------- host orchestration -----------------------------------------
extern "C" void kernel_launch(void* const* d_in, const int* in_sizes, int n_in,
                              void* d_out, int out_size)
{
    (void)in_sizes; (void)n_in; (void)out_size;
    const float* xs    = (const float*)d_in[0];
    const float* xt5   = (const float*)d_in[1] + (size_t)(TT - 1) * NT * FF;
    const float* ea    = (const float*)d_in[2];
    const float* nmask = (const float*)d_in[3];
    const float* emask = (const float*)d_in[4];
    const int*   ei    = (const int*)d_in[5];
    const int*   src5  = ei + (size_t)(TT - 1) * 2 * EE;
    const int*   dst5  = src5 + EE;
    const float* W1s5  = (const float*)d_in[6]  + (size_t)(TT - 1) * FF * HCC;
    const float* W1d5  = (const float*)d_in[7]  + (size_t)(TT - 1) * FF * HCC;
    const float* a1_5  = (const float*)d_in[8]  + (size_t)(TT - 1) * HCC;
    const float* W2s5  = (const float*)d_in[9]  + (size_t)(TT - 1) * FF * HCC;
    const float* W2d5  = (const float*)d_in[10] + (size_t)(TT - 1) * HCC * HCC;
    const float* a2_5  = (const float*)d_in[11] + (size_t)(TT - 1) * HCC;
    const float* Wc    = (const float*)d_in[12];
    const float* bc    = (const float*)d_in[13];
    float* out = (float*)d_out;

    float *hs1, *hd1, *h1, *hs2, *hd2, *out2, *esc, *wb, *den1, *den2, *pooled, *agg;
    unsigned *emx1, *emx2;
    cudaGetSymbolAddress((void**)&hs1,    g_hs1);
    cudaGetSymbolAddress((void**)&hd1,    g_hd1);
    cudaGetSymbolAddress((void**)&h1,     g_h1);
    cudaGetSymbolAddress((void**)&hs2,    g_hs2);
    cudaGetSymbolAddress((void**)&hd2,    g_hd2);
    cudaGetSymbolAddress((void**)&out2,   g_out2);
    cudaGetSymbolAddress((void**)&esc,    g_escore);
    cudaGetSymbolAddress((void**)&wb,     g_wbuf);
    cudaGetSymbolAddress((void**)&den1,   g_denom1);
    cudaGetSymbolAddress((void**)&den2,   g_denom2);
    cudaGetSymbolAddress((void**)&emx1,   g_emax1);
    cudaGetSymbolAddress((void**)&emx2,   g_emax2);
    cudaGetSymbolAddress((void**)&pooled, g_pooled);
    cudaGetSymbolAddress((void**)&agg,    g_agg);

    dim3 gemm_grid(HCC / 128, NPAD / 128);                       // (2, 157)
    const int EW_BLOCKS = (int)(((size_t)EE * 32 + 255) / 256);  // warp-per-edge kernels
    const int E_BLOCKS  = (EE + 255) / 256;

    init_kernel<<<1024, 256>>>();

    // layer-1 projections + layer-2 source projection (independent of layer 1)
    sgemm_tc<1, 0><<<gemm_grid, 256>>>(xs,  W1s5, hs1, nmask, NS, FF);
    sgemm_tc<1, 0><<<gemm_grid, 256>>>(xt5, W1d5, hd1, nmask, NT, FF);
    sgemm_tc<1, 0><<<gemm_grid, 256>>>(xs,  W2s5, hs2, nmask, NS, FF);

    // layer-1 attention
    edge_score_max<<<EW_BLOCKS, 256>>>(src5, dst5, hs1, hd1, a1_5, esc, emx1);
    edge_softmax_denom<<<E_BLOCKS, 256>>>(dst5, esc, emx1, emask, wb, den1);
    edge_aggregate<<<EW_BLOCKS, 256>>>(src5, dst5, hs1, wb, den1, h1);

    // layer-2 target projection: relu(h1) @ W2_dst  (relu folded into A-load)
    sgemm_tc<0, 1><<<gemm_grid, 256>>>(h1, W2d5, hd2, nullptr, NT, HCC);

    // layer-2 attention
    edge_score_max<<<EW_BLOCKS, 256>>>(src5, dst5, hs2, hd2, a2_5, esc, emx2);
    edge_softmax_denom<<<E_BLOCKS, 256>>>(dst5, esc, emx2, emask, wb, den2);
    edge_aggregate<<<EW_BLOCKS, 256>>>(src5, dst5, hs2, wb, den2, out2);

    // head
    pool_kernel<<<128, 256>>>(out2, pooled);
    edge_attr_agg<<<dim3(32, TT), 256>>>(ea, agg);
    finalize_kernel<<<1, 256>>>(Wc, bc, out);
}